// round 8
// baseline (speedup 1.0000x reference)
#include <cuda_runtime.h>
#include <math.h>

#define H       128
#define TI      32    // interior points per block (4 per warp, as 2 pairs)
#define NP      (TI / 2)
#define TB      32    // boundary points per block
#define THREADS 256

typedef unsigned long long ull;

// Per-block partial sums (deterministic two-stage reduction; no device mallocs)
__device__ float g_part_int[65536];
__device__ float g_part_bd[8192];

// Duplicated weights for point-paired FFMA2: Wd[k*H+j] = (W[k][j], W[k][j]).
// 128 KB per layer, written by a prologue kernel each launch (deterministic).
__device__ ull g_W1d[H * H];
__device__ ull g_W2d[H * H];

// Accurate tanh independent of -use_fast_math lowering of tanhf.
__device__ __forceinline__ float my_tanh(float x)
{
    float ax = fabsf(x);
    float t  = __expf(-2.0f * ax);
    float r  = (1.0f - t) / (1.0f + t);
    return copysignf(r, x);
}

// ---- packed fp32x2 helpers (sm_103a FFMA2 path) ----
__device__ __forceinline__ void ffma2(ull& acc, ull a, ull w)
{
    asm("fma.rn.f32x2 %0, %1, %2, %0;" : "+l"(acc) : "l"(a), "l"(w));
}
__device__ __forceinline__ ull packf2(float lo, float hi)
{
    ull r;
    asm("mov.b64 %0, {%1, %2};" : "=l"(r) : "f"(lo), "f"(hi));
    return r;
}
__device__ __forceinline__ void unpackf2(ull v, float& lo, float& hi)
{
    asm("mov.b64 {%0, %1}, %2;" : "=f"(lo), "=f"(hi) : "l"(v));
}

// ---------------------------------------------------------------------------
// Prologue: duplicate W into 64-bit (w,w) pairs (one-time per launch).
// ---------------------------------------------------------------------------
__global__ void pinn_pack(const float* __restrict__ W1,
                          const float* __restrict__ W2)
{
    int i = blockIdx.x * blockDim.x + threadIdx.x;
    if (i < H * H) {
        g_W1d[i] = packf2(W1[i], W1[i]);
        g_W2d[i] = packf2(W2[i], W2[i]);
    }
}

// ---------------------------------------------------------------------------
// Accumulate 4 channels x 2 point-pairs x 4 units with point-paired FFMA2.
// Each 64-bit accumulator holds (acc_point0, acc_point1) — per-point math is
// bit-identical to scalar FMA. Activations live in smem as point-pair ulls:
// A2[(c*NP + pq)*H + k] = (a_p0[k], a_p1[k]). Weights come pre-duplicated
// from g_W*d — LDG.128 yields 2 dup pairs, zero packing MOVs.
// ---------------------------------------------------------------------------
__device__ __forceinline__ void accum4p(const ull* __restrict__ in,
                                        const ull* __restrict__ Wd,
                                        int j4, int pq0,
                                        ull acc2[4][2][4])
{
#pragma unroll
    for (int c = 0; c < 4; c++)
#pragma unroll
        for (int pr = 0; pr < 2; pr++)
#pragma unroll
            for (int u = 0; u < 4; u++) acc2[c][pr][u] = 0ULL;

#pragma unroll 1
    for (int k = 0; k < H; k += 2) {
        const ulonglong2 wa = *reinterpret_cast<const ulonglong2*>(
            &Wd[(k + 0) * H + j4]);         // dup pairs: units j4, j4+1 (row k)
        const ulonglong2 wb = *reinterpret_cast<const ulonglong2*>(
            &Wd[(k + 0) * H + j4 + 2]);     // units j4+2, j4+3 (row k)
        const ulonglong2 wc = *reinterpret_cast<const ulonglong2*>(
            &Wd[(k + 1) * H + j4]);         // row k+1
        const ulonglong2 wd2 = *reinterpret_cast<const ulonglong2*>(
            &Wd[(k + 1) * H + j4 + 2]);

#pragma unroll
        for (int c = 0; c < 4; c++) {
#pragma unroll
            for (int pr = 0; pr < 2; pr++) {
                const ulonglong2 av = *reinterpret_cast<const ulonglong2*>(
                    &in[(c * NP + pq0 + pr) * H + k]);
                ffma2(acc2[c][pr][0], av.x, wa.x);
                ffma2(acc2[c][pr][1], av.x, wa.y);
                ffma2(acc2[c][pr][2], av.x, wb.x);
                ffma2(acc2[c][pr][3], av.x, wb.y);
                ffma2(acc2[c][pr][0], av.y, wc.x);
                ffma2(acc2[c][pr][1], av.y, wc.y);
                ffma2(acc2[c][pr][2], av.y, wd2.x);
                ffma2(acc2[c][pr][3], av.y, wd2.y);
            }
        }
    }
}

// ---------------------------------------------------------------------------
// Interior: 4-channel Taylor-mode Laplacian (v, gx, gy, L = uxx+uyy),
// point-paired FFMA2, warp-autonomous pipeline.
// ---------------------------------------------------------------------------
__global__ __launch_bounds__(THREADS, 2)
void pinn_interior(const float* __restrict__ xy, const float* __restrict__ f,
                   const float* __restrict__ W0, const float* __restrict__ b0,
                   const float* __restrict__ b1,
                   const float* __restrict__ b2,
                   const float* __restrict__ W3, int n)
{
    extern __shared__ __align__(16) ull A2[];          // 4*NP*H ulls = 64 KB
    float* slap = reinterpret_cast<float*>(A2 + 4 * NP * H);

    const int tid  = threadIdx.x;
    const int t    = tid & 31;        // unit group: j = 4t..4t+3
    const int j4   = t * 4;
    const int w    = tid >> 5;
    const int pq0  = w * 2;           // warp owns pairs pq0, pq0+1 (4 points)
    const int base = blockIdx.x * TI;

    // per-warp broadcast loads of this warp's 4 points
    float xin[4], yin[4];
#pragma unroll
    for (int p = 0; p < 4; p++) {
        int pt = base + pq0 * 2 + p; if (pt > n - 1) pt = n - 1;
        xin[p] = __ldg(&xy[pt * 2 + 0]);
        yin[p] = __ldg(&xy[pt * 2 + 1]);
    }

    // ---- layer 0: (x,y) -> 128 with derivative seeding, pair-packed ----
    {
        const float4 wxv = *reinterpret_cast<const float4*>(&W0[j4]);
        const float4 wyv = *reinterpret_cast<const float4*>(&W0[H + j4]);
        const float4 bbv = *reinterpret_cast<const float4*>(&b0[j4]);
        const float wx[4] = {wxv.x, wxv.y, wxv.z, wxv.w};
        const float wy[4] = {wyv.x, wyv.y, wyv.z, wyv.w};
        const float bj[4] = {bbv.x, bbv.y, bbv.z, bbv.w};
#pragma unroll
        for (int pr = 0; pr < 2; pr++) {
            const int pq = pq0 + pr;
            const float x0 = xin[pr * 2 + 0], y0 = yin[pr * 2 + 0];
            const float x1 = xin[pr * 2 + 1], y1 = yin[pr * 2 + 1];
            ull o[4][4];
#pragma unroll
            for (int u = 0; u < 4; u++) {
                float zv0 = fmaf(x0, wx[u], fmaf(y0, wy[u], bj[u]));
                float a0  = my_tanh(zv0);
                float t10 = 1.0f - a0 * a0;
                float t20 = -2.0f * a0 * t10;
                float zv1 = fmaf(x1, wx[u], fmaf(y1, wy[u], bj[u]));
                float a1  = my_tanh(zv1);
                float t11 = 1.0f - a1 * a1;
                float t21 = -2.0f * a1 * t11;
                float ww  = fmaf(wx[u], wx[u], wy[u] * wy[u]);
                o[0][u] = packf2(a0, a1);
                o[1][u] = packf2(t10 * wx[u], t11 * wx[u]);
                o[2][u] = packf2(t10 * wy[u], t11 * wy[u]);
                o[3][u] = packf2(t20 * ww, t21 * ww);
            }
#pragma unroll
            for (int c = 0; c < 4; c++) {
                *reinterpret_cast<ulonglong2*>(&A2[(c * NP + pq) * H + j4]) =
                    make_ulonglong2(o[c][0], o[c][1]);
                *reinterpret_cast<ulonglong2*>(&A2[(c * NP + pq) * H + j4 + 2]) =
                    make_ulonglong2(o[c][2], o[c][3]);
            }
        }
    }
    __syncwarp();

    // ---- layer 1 (in-place: read A2, then overwrite A2) ----
    {
        ull acc2[4][2][4];
        accum4p(A2, g_W1d, j4, pq0, acc2);
        __syncwarp();

        const float4 bb = *reinterpret_cast<const float4*>(&b1[j4]);
        const float bj[4] = {bb.x, bb.y, bb.z, bb.w};
#pragma unroll
        for (int pr = 0; pr < 2; pr++) {
            const int pq = pq0 + pr;
            ull o[4][4];
#pragma unroll
            for (int u = 0; u < 4; u++) {
                float zv0, zv1, gx0, gx1, gy0, gy1, zL0, zL1;
                unpackf2(acc2[0][pr][u], zv0, zv1);
                unpackf2(acc2[1][pr][u], gx0, gx1);
                unpackf2(acc2[2][pr][u], gy0, gy1);
                unpackf2(acc2[3][pr][u], zL0, zL1);

                float a0  = my_tanh(zv0 + bj[u]);
                float t10 = 1.0f - a0 * a0;
                float t20 = -2.0f * a0 * t10;
                float a1  = my_tanh(zv1 + bj[u]);
                float t11 = 1.0f - a1 * a1;
                float t21 = -2.0f * a1 * t11;

                o[0][u] = packf2(a0, a1);
                o[1][u] = packf2(t10 * gx0, t11 * gx1);
                o[2][u] = packf2(t10 * gy0, t11 * gy1);
                o[3][u] = packf2(
                    fmaf(t20, fmaf(gx0, gx0, gy0 * gy0), t10 * zL0),
                    fmaf(t21, fmaf(gx1, gx1, gy1 * gy1), t11 * zL1));
            }
#pragma unroll
            for (int c = 0; c < 4; c++) {
                *reinterpret_cast<ulonglong2*>(&A2[(c * NP + pq) * H + j4]) =
                    make_ulonglong2(o[c][0], o[c][1]);
                *reinterpret_cast<ulonglong2*>(&A2[(c * NP + pq) * H + j4 + 2]) =
                    make_ulonglong2(o[c][2], o[c][3]);
            }
        }
    }
    __syncwarp();

    // ---- layer 2 fused with output projection: lap = W3 . L_out ----
    {
        ull acc2[4][2][4];
        accum4p(A2, g_W2d, j4, pq0, acc2);

        const float4 bbv = *reinterpret_cast<const float4*>(&b2[j4]);
        const float4 w3v = *reinterpret_cast<const float4*>(&W3[j4]);
        const float bj[4] = {bbv.x, bbv.y, bbv.z, bbv.w};
        const float w3[4] = {w3v.x, w3v.y, w3v.z, w3v.w};

#pragma unroll
        for (int pr = 0; pr < 2; pr++) {
            float s0 = 0.0f, s1 = 0.0f;
#pragma unroll
            for (int u = 0; u < 4; u++) {
                float zv0, zv1, gx0, gx1, gy0, gy1, zL0, zL1;
                unpackf2(acc2[0][pr][u], zv0, zv1);
                unpackf2(acc2[1][pr][u], gx0, gx1);
                unpackf2(acc2[2][pr][u], gy0, gy1);
                unpackf2(acc2[3][pr][u], zL0, zL1);

                float a0  = my_tanh(zv0 + bj[u]);
                float t10 = 1.0f - a0 * a0;
                float t20 = -2.0f * a0 * t10;
                float L0  = fmaf(t20, fmaf(gx0, gx0, gy0 * gy0), t10 * zL0);
                s0 = fmaf(L0, w3[u], s0);

                float a1  = my_tanh(zv1 + bj[u]);
                float t11 = 1.0f - a1 * a1;
                float t21 = -2.0f * a1 * t11;
                float L1  = fmaf(t21, fmaf(gx1, gx1, gy1 * gy1), t11 * zL1);
                s1 = fmaf(L1, w3[u], s1);
            }
#pragma unroll
            for (int off = 16; off > 0; off >>= 1) {
                s0 += __shfl_xor_sync(0xffffffffu, s0, off);
                s1 += __shfl_xor_sync(0xffffffffu, s1, off);
            }
            if (t == 0) {
                slap[(pq0 + pr) * 2 + 0] = s0;
                slap[(pq0 + pr) * 2 + 1] = s1;
            }
        }
    }
    __syncthreads();   // only block-wide barrier: before final reduction

    if (tid == 0) {
        float ssum = 0.0f;
#pragma unroll
        for (int p = 0; p < TI; p++) {
            int idx = base + p;
            if (idx < n) {
                float d = slap[p] - f[idx];
                ssum = fmaf(d, d, ssum);
            }
        }
        g_part_int[blockIdx.x] = ssum;
    }
}

// ---------------------------------------------------------------------------
// Boundary: plain forward + squared residual partial sums (small workload).
// ---------------------------------------------------------------------------
__device__ __forceinline__ void hidden1(const float* __restrict__ in,
                                        float* __restrict__ outp,
                                        const float* __restrict__ W,
                                        const float* __restrict__ b,
                                        int j, int p0)
{
    float acc[TB / 2];
#pragma unroll
    for (int p = 0; p < TB / 2; p++) acc[p] = 0.0f;

#pragma unroll 1
    for (int k = 0; k < H; k += 4) {
        const float w0 = W[(k + 0) * H + j];
        const float w1 = W[(k + 1) * H + j];
        const float w2 = W[(k + 2) * H + j];
        const float w3 = W[(k + 3) * H + j];
#pragma unroll
        for (int p = 0; p < TB / 2; p++) {
            const float4 a = *reinterpret_cast<const float4*>(
                &in[(p0 + p) * H + k]);
            acc[p] = fmaf(a.x, w0,
                      fmaf(a.y, w1,
                       fmaf(a.z, w2,
                        fmaf(a.w, w3, acc[p]))));
        }
    }

    const float bj = b[j];
#pragma unroll
    for (int p = 0; p < TB / 2; p++)
        outp[(p0 + p) * H + j] = my_tanh(acc[p] + bj);
}

__global__ __launch_bounds__(THREADS)
void pinn_boundary(const float* __restrict__ xy, const float* __restrict__ g,
                   const float* __restrict__ W0, const float* __restrict__ b0,
                   const float* __restrict__ W1, const float* __restrict__ b1,
                   const float* __restrict__ W2, const float* __restrict__ b2,
                   const float* __restrict__ W3, const float* __restrict__ b3,
                   int n)
{
    __shared__ __align__(16) float A[TB * H];
    __shared__ __align__(16) float B[TB * H];
    __shared__ float sxy[TB * 2];
    __shared__ float red[TB];

    const int tid  = threadIdx.x;
    const int j    = tid & (H - 1);
    const int p0   = (tid >> 7) * (TB / 2);
    const int base = blockIdx.x * TB;

    if (tid < TB * 2) {
        int pt = base + (tid >> 1);
        if (pt > n - 1) pt = n - 1;
        sxy[tid] = xy[pt * 2 + (tid & 1)];
    }
    __syncthreads();

    {
        const float w0x = W0[j];
        const float w0y = W0[H + j];
        const float bj  = b0[j];
#pragma unroll
        for (int p = 0; p < TB / 2; p++) {
            const int pp = p0 + p;
            float x = sxy[pp * 2 + 0];
            float y = sxy[pp * 2 + 1];
            A[pp * H + j] = my_tanh(fmaf(x, w0x, fmaf(y, w0y, bj)));
        }
    }
    __syncthreads();

    hidden1(A, B, W1, b1, j, p0);
    __syncthreads();
    hidden1(B, A, W2, b2, j, p0);
    __syncthreads();

    if (tid < TB) {
        float v = b3[0];
        for (int k = 0; k < H; k++)
            v = fmaf(A[tid * H + k], W3[k], v);
        int idx = base + tid;
        if (idx < n) {
            float d = v - g[idx];
            red[tid] = d * d;
        } else {
            red[tid] = 0.0f;
        }
    }
    __syncthreads();

    if (tid == 0) {
        float s = 0.0f;
#pragma unroll
        for (int p = 0; p < TB; p++) s += red[p];
        g_part_bd[blockIdx.x] = s;
    }
}

// ---------------------------------------------------------------------------
// Final deterministic reduction -> out[0] = loss_bound, out[1] = loss_f
// ---------------------------------------------------------------------------
__global__ __launch_bounds__(THREADS)
void pinn_finalize(float* __restrict__ out, int nbi, int nbb,
                   int n_int, int n_bd)
{
    __shared__ float s[THREADS];
    const int tid = threadIdx.x;

    float a = 0.0f;
    for (int i = tid; i < nbi; i += THREADS) a += g_part_int[i];
    s[tid] = a;
    __syncthreads();
    for (int st = THREADS / 2; st > 0; st >>= 1) {
        if (tid < st) s[tid] += s[tid + st];
        __syncthreads();
    }
    float loss_f = 0.0f;
    if (tid == 0) loss_f = s[0] * (0.5f / (float)n_int);
    __syncthreads();

    float bsm = 0.0f;
    for (int i = tid; i < nbb; i += THREADS) bsm += g_part_bd[i];
    s[tid] = bsm;
    __syncthreads();
    for (int st = THREADS / 2; st > 0; st >>= 1) {
        if (tid < st) s[tid] += s[tid + st];
        __syncthreads();
    }
    if (tid == 0) {
        out[0] = s[0] * (0.5f / (float)n_bd); // loss_bound
        out[1] = loss_f;                      // loss_f
    }
}

// ---------------------------------------------------------------------------
extern "C" void kernel_launch(void* const* d_in, const int* in_sizes, int n_in,
                              void* d_out, int out_size)
{
    const float* xy_int = (const float*)d_in[0];
    const float* f      = (const float*)d_in[1];
    const float* xy_bd  = (const float*)d_in[2];
    const float* g      = (const float*)d_in[3];
    const float* W0     = (const float*)d_in[4];
    const float* b0     = (const float*)d_in[5];
    const float* W1     = (const float*)d_in[6];
    const float* b1     = (const float*)d_in[7];
    const float* W2     = (const float*)d_in[8];
    const float* b2     = (const float*)d_in[9];
    const float* W3     = (const float*)d_in[10];
    const float* b3     = (const float*)d_in[11];

    const int n_int = in_sizes[0] / 2;
    const int n_bd  = in_sizes[2] / 2;

    int gi = (n_int + TI - 1) / TI;
    int gb = (n_bd + TB - 1) / TB;
    if (gi > 65536) gi = 65536; // scratch bound (dataset: 8192)
    if (gb > 8192)  gb = 8192;  // scratch bound (dataset: 512)

    // dynamic smem: pair-packed activations + lap scratch
    const int smem_bytes = 4 * NP * H * (int)sizeof(ull)
                         + TI * (int)sizeof(float);   // 65664 B

    cudaFuncSetAttribute(pinn_interior,
                         cudaFuncAttributeMaxDynamicSharedMemorySize,
                         smem_bytes);

    pinn_pack<<<(H * H + 255) / 256, 256>>>(W1, W2);
    pinn_interior<<<gi, THREADS, smem_bytes>>>(xy_int, f, W0, b0, b1, b2,
                                               W3, n_int);
    pinn_boundary<<<gb, THREADS>>>(xy_bd, g, W0, b0, W1, b1, W2, b2, W3, b3,
                                   n_bd);
    pinn_finalize<<<1, THREADS>>>((float*)d_out, gi, gb, n_int, n_bd);
}

// round 9
// speedup vs baseline: 1.2102x; 1.2102x over previous
#include <cuda_runtime.h>
#include <math.h>

#define H       128
#define TI      32    // interior points per block (4 per warp, as 2 pairs)
#define NP      (TI / 2)
#define TB      32    // boundary points per block
#define THREADS 256

typedef unsigned long long ull;

// Per-block partial sums (deterministic two-stage reduction; no device mallocs)
__device__ float g_part_int[65536];
__device__ float g_part_bd[8192];

// Accurate tanh independent of -use_fast_math lowering of tanhf.
__device__ __forceinline__ float my_tanh(float x)
{
    float ax = fabsf(x);
    float t  = __expf(-2.0f * ax);
    float r  = (1.0f - t) / (1.0f + t);
    return copysignf(r, x);
}

// ---- packed fp32x2 helpers (sm_103a FFMA2 path) ----
__device__ __forceinline__ void ffma2(ull& acc, ull a, ull w)
{
    asm("fma.rn.f32x2 %0, %1, %2, %0;" : "+l"(acc) : "l"(a), "l"(w));
}
__device__ __forceinline__ ull packf2(float lo, float hi)
{
    ull r;
    asm("mov.b64 %0, {%1, %2};" : "=l"(r) : "f"(lo), "f"(hi));
    return r;
}
__device__ __forceinline__ void unpackf2(ull v, float& lo, float& hi)
{
    asm("mov.b64 {%0, %1}, %2;" : "=f"(lo), "=f"(hi) : "l"(v));
}

// ---------------------------------------------------------------------------
// Accumulate 4 channels x 2 point-pairs x 4 units with point-paired FFMA2.
// Each 64-bit accumulator holds (acc_point0, acc_point1) — per-point math is
// bit-identical to scalar FMA. Activations live in smem as point-pair ulls:
// A2[(c*NP + pq)*H + k] = (a_p0[k], a_p1[k]). Weights: scalar float4 LDG.128
// (warp-contiguous 512B rows, L1-resident), duplicated in registers.
// k-loop unrolled x2; per-(c,pr) smem bases hoisted for immediate addressing.
// ---------------------------------------------------------------------------
__device__ __forceinline__ void accum4p(const ull* __restrict__ in,
                                        const float* __restrict__ W,
                                        int j4, int pq0,
                                        ull acc2[4][2][4])
{
#pragma unroll
    for (int c = 0; c < 4; c++)
#pragma unroll
        for (int pr = 0; pr < 2; pr++)
#pragma unroll
            for (int u = 0; u < 4; u++) acc2[c][pr][u] = 0ULL;

    // hoisted per-(c,pr) activation row bases
    const ull* arow[4][2];
#pragma unroll
    for (int c = 0; c < 4; c++)
#pragma unroll
        for (int pr = 0; pr < 2; pr++)
            arow[c][pr] = &in[(c * NP + pq0 + pr) * H];

    const float* wrow = &W[j4];

#pragma unroll 2
    for (int k = 0; k < H; k += 2) {
        const float4 wA = *reinterpret_cast<const float4*>(&wrow[(k + 0) * H]);
        const float4 wB = *reinterpret_cast<const float4*>(&wrow[(k + 1) * H]);
        ull wp0[4], wp1[4];
        wp0[0] = packf2(wA.x, wA.x); wp0[1] = packf2(wA.y, wA.y);
        wp0[2] = packf2(wA.z, wA.z); wp0[3] = packf2(wA.w, wA.w);
        wp1[0] = packf2(wB.x, wB.x); wp1[1] = packf2(wB.y, wB.y);
        wp1[2] = packf2(wB.z, wB.z); wp1[3] = packf2(wB.w, wB.w);

#pragma unroll
        for (int c = 0; c < 4; c++) {
#pragma unroll
            for (int pr = 0; pr < 2; pr++) {
                const ulonglong2 av = *reinterpret_cast<const ulonglong2*>(
                    &arow[c][pr][k]);
#pragma unroll
                for (int u = 0; u < 4; u++) {
                    ffma2(acc2[c][pr][u], av.x, wp0[u]);
                    ffma2(acc2[c][pr][u], av.y, wp1[u]);
                }
            }
        }
    }
}

// ---------------------------------------------------------------------------
// Interior: 4-channel Taylor-mode Laplacian (v, gx, gy, L = uxx+uyy),
// point-paired FFMA2, warp-autonomous pipeline.
// ---------------------------------------------------------------------------
__global__ __launch_bounds__(THREADS, 2)
void pinn_interior(const float* __restrict__ xy, const float* __restrict__ f,
                   const float* __restrict__ W0, const float* __restrict__ b0,
                   const float* __restrict__ W1, const float* __restrict__ b1,
                   const float* __restrict__ W2, const float* __restrict__ b2,
                   const float* __restrict__ W3, int n)
{
    extern __shared__ __align__(16) ull A2[];          // 4*NP*H ulls = 64 KB
    float* slap = reinterpret_cast<float*>(A2 + 4 * NP * H);

    const int tid  = threadIdx.x;
    const int t    = tid & 31;        // unit group: j = 4t..4t+3
    const int j4   = t * 4;
    const int w    = tid >> 5;
    const int pq0  = w * 2;           // warp owns pairs pq0, pq0+1 (4 points)
    const int base = blockIdx.x * TI;

    // per-warp broadcast loads of this warp's 4 points
    float xin[4], yin[4];
#pragma unroll
    for (int p = 0; p < 4; p++) {
        int pt = base + pq0 * 2 + p; if (pt > n - 1) pt = n - 1;
        xin[p] = __ldg(&xy[pt * 2 + 0]);
        yin[p] = __ldg(&xy[pt * 2 + 1]);
    }

    // ---- layer 0: (x,y) -> 128 with derivative seeding, pair-packed ----
    {
        const float4 wxv = *reinterpret_cast<const float4*>(&W0[j4]);
        const float4 wyv = *reinterpret_cast<const float4*>(&W0[H + j4]);
        const float4 bbv = *reinterpret_cast<const float4*>(&b0[j4]);
        const float wx[4] = {wxv.x, wxv.y, wxv.z, wxv.w};
        const float wy[4] = {wyv.x, wyv.y, wyv.z, wyv.w};
        const float bj[4] = {bbv.x, bbv.y, bbv.z, bbv.w};
#pragma unroll
        for (int pr = 0; pr < 2; pr++) {
            const int pq = pq0 + pr;
            const float x0 = xin[pr * 2 + 0], y0 = yin[pr * 2 + 0];
            const float x1 = xin[pr * 2 + 1], y1 = yin[pr * 2 + 1];
            ull o[4][4];
#pragma unroll
            for (int u = 0; u < 4; u++) {
                float zv0 = fmaf(x0, wx[u], fmaf(y0, wy[u], bj[u]));
                float a0  = my_tanh(zv0);
                float t10 = 1.0f - a0 * a0;
                float t20 = -2.0f * a0 * t10;
                float zv1 = fmaf(x1, wx[u], fmaf(y1, wy[u], bj[u]));
                float a1  = my_tanh(zv1);
                float t11 = 1.0f - a1 * a1;
                float t21 = -2.0f * a1 * t11;
                float ww  = fmaf(wx[u], wx[u], wy[u] * wy[u]);
                o[0][u] = packf2(a0, a1);
                o[1][u] = packf2(t10 * wx[u], t11 * wx[u]);
                o[2][u] = packf2(t10 * wy[u], t11 * wy[u]);
                o[3][u] = packf2(t20 * ww, t21 * ww);
            }
#pragma unroll
            for (int c = 0; c < 4; c++) {
                *reinterpret_cast<ulonglong2*>(&A2[(c * NP + pq) * H + j4]) =
                    make_ulonglong2(o[c][0], o[c][1]);
                *reinterpret_cast<ulonglong2*>(&A2[(c * NP + pq) * H + j4 + 2]) =
                    make_ulonglong2(o[c][2], o[c][3]);
            }
        }
    }
    __syncwarp();

    // ---- layer 1 (in-place: read A2, then overwrite A2) ----
    {
        ull acc2[4][2][4];
        accum4p(A2, W1, j4, pq0, acc2);
        __syncwarp();

        const float4 bb = *reinterpret_cast<const float4*>(&b1[j4]);
        const float bj[4] = {bb.x, bb.y, bb.z, bb.w};
#pragma unroll
        for (int pr = 0; pr < 2; pr++) {
            const int pq = pq0 + pr;
            ull o[4][4];
#pragma unroll
            for (int u = 0; u < 4; u++) {
                float zv0, zv1, gx0, gx1, gy0, gy1, zL0, zL1;
                unpackf2(acc2[0][pr][u], zv0, zv1);
                unpackf2(acc2[1][pr][u], gx0, gx1);
                unpackf2(acc2[2][pr][u], gy0, gy1);
                unpackf2(acc2[3][pr][u], zL0, zL1);

                float a0  = my_tanh(zv0 + bj[u]);
                float t10 = 1.0f - a0 * a0;
                float t20 = -2.0f * a0 * t10;
                float a1  = my_tanh(zv1 + bj[u]);
                float t11 = 1.0f - a1 * a1;
                float t21 = -2.0f * a1 * t11;

                o[0][u] = packf2(a0, a1);
                o[1][u] = packf2(t10 * gx0, t11 * gx1);
                o[2][u] = packf2(t10 * gy0, t11 * gy1);
                o[3][u] = packf2(
                    fmaf(t20, fmaf(gx0, gx0, gy0 * gy0), t10 * zL0),
                    fmaf(t21, fmaf(gx1, gx1, gy1 * gy1), t11 * zL1));
            }
#pragma unroll
            for (int c = 0; c < 4; c++) {
                *reinterpret_cast<ulonglong2*>(&A2[(c * NP + pq) * H + j4]) =
                    make_ulonglong2(o[c][0], o[c][1]);
                *reinterpret_cast<ulonglong2*>(&A2[(c * NP + pq) * H + j4 + 2]) =
                    make_ulonglong2(o[c][2], o[c][3]);
            }
        }
    }
    __syncwarp();

    // ---- layer 2 fused with output projection: lap = W3 . L_out ----
    {
        ull acc2[4][2][4];
        accum4p(A2, W2, j4, pq0, acc2);

        const float4 bbv = *reinterpret_cast<const float4*>(&b2[j4]);
        const float4 w3v = *reinterpret_cast<const float4*>(&W3[j4]);
        const float bj[4] = {bbv.x, bbv.y, bbv.z, bbv.w};
        const float w3[4] = {w3v.x, w3v.y, w3v.z, w3v.w};

#pragma unroll
        for (int pr = 0; pr < 2; pr++) {
            float s0 = 0.0f, s1 = 0.0f;
#pragma unroll
            for (int u = 0; u < 4; u++) {
                float zv0, zv1, gx0, gx1, gy0, gy1, zL0, zL1;
                unpackf2(acc2[0][pr][u], zv0, zv1);
                unpackf2(acc2[1][pr][u], gx0, gx1);
                unpackf2(acc2[2][pr][u], gy0, gy1);
                unpackf2(acc2[3][pr][u], zL0, zL1);

                float a0  = my_tanh(zv0 + bj[u]);
                float t10 = 1.0f - a0 * a0;
                float t20 = -2.0f * a0 * t10;
                float L0  = fmaf(t20, fmaf(gx0, gx0, gy0 * gy0), t10 * zL0);
                s0 = fmaf(L0, w3[u], s0);

                float a1  = my_tanh(zv1 + bj[u]);
                float t11 = 1.0f - a1 * a1;
                float t21 = -2.0f * a1 * t11;
                float L1  = fmaf(t21, fmaf(gx1, gx1, gy1 * gy1), t11 * zL1);
                s1 = fmaf(L1, w3[u], s1);
            }
#pragma unroll
            for (int off = 16; off > 0; off >>= 1) {
                s0 += __shfl_xor_sync(0xffffffffu, s0, off);
                s1 += __shfl_xor_sync(0xffffffffu, s1, off);
            }
            if (t == 0) {
                slap[(pq0 + pr) * 2 + 0] = s0;
                slap[(pq0 + pr) * 2 + 1] = s1;
            }
        }
    }
    __syncthreads();   // only block-wide barrier: before final reduction

    if (tid == 0) {
        float ssum = 0.0f;
#pragma unroll
        for (int p = 0; p < TI; p++) {
            int idx = base + p;
            if (idx < n) {
                float d = slap[p] - f[idx];
                ssum = fmaf(d, d, ssum);
            }
        }
        g_part_int[blockIdx.x] = ssum;
    }
}

// ---------------------------------------------------------------------------
// Boundary: plain forward + squared residual partial sums (small workload).
// ---------------------------------------------------------------------------
__device__ __forceinline__ void hidden1(const float* __restrict__ in,
                                        float* __restrict__ outp,
                                        const float* __restrict__ W,
                                        const float* __restrict__ b,
                                        int j, int p0)
{
    float acc[TB / 2];
#pragma unroll
    for (int p = 0; p < TB / 2; p++) acc[p] = 0.0f;

#pragma unroll 1
    for (int k = 0; k < H; k += 4) {
        const float w0 = W[(k + 0) * H + j];
        const float w1 = W[(k + 1) * H + j];
        const float w2 = W[(k + 2) * H + j];
        const float w3 = W[(k + 3) * H + j];
#pragma unroll
        for (int p = 0; p < TB / 2; p++) {
            const float4 a = *reinterpret_cast<const float4*>(
                &in[(p0 + p) * H + k]);
            acc[p] = fmaf(a.x, w0,
                      fmaf(a.y, w1,
                       fmaf(a.z, w2,
                        fmaf(a.w, w3, acc[p]))));
        }
    }

    const float bj = b[j];
#pragma unroll
    for (int p = 0; p < TB / 2; p++)
        outp[(p0 + p) * H + j] = my_tanh(acc[p] + bj);
}

__global__ __launch_bounds__(THREADS)
void pinn_boundary(const float* __restrict__ xy, const float* __restrict__ g,
                   const float* __restrict__ W0, const float* __restrict__ b0,
                   const float* __restrict__ W1, const float* __restrict__ b1,
                   const float* __restrict__ W2, const float* __restrict__ b2,
                   const float* __restrict__ W3, const float* __restrict__ b3,
                   int n)
{
    __shared__ __align__(16) float A[TB * H];
    __shared__ __align__(16) float B[TB * H];
    __shared__ float sxy[TB * 2];
    __shared__ float red[TB];

    const int tid  = threadIdx.x;
    const int j    = tid & (H - 1);
    const int p0   = (tid >> 7) * (TB / 2);
    const int base = blockIdx.x * TB;

    if (tid < TB * 2) {
        int pt = base + (tid >> 1);
        if (pt > n - 1) pt = n - 1;
        sxy[tid] = xy[pt * 2 + (tid & 1)];
    }
    __syncthreads();

    {
        const float w0x = W0[j];
        const float w0y = W0[H + j];
        const float bj  = b0[j];
#pragma unroll
        for (int p = 0; p < TB / 2; p++) {
            const int pp = p0 + p;
            float x = sxy[pp * 2 + 0];
            float y = sxy[pp * 2 + 1];
            A[pp * H + j] = my_tanh(fmaf(x, w0x, fmaf(y, w0y, bj)));
        }
    }
    __syncthreads();

    hidden1(A, B, W1, b1, j, p0);
    __syncthreads();
    hidden1(B, A, W2, b2, j, p0);
    __syncthreads();

    if (tid < TB) {
        float v = b3[0];
        for (int k = 0; k < H; k++)
            v = fmaf(A[tid * H + k], W3[k], v);
        int idx = base + tid;
        if (idx < n) {
            float d = v - g[idx];
            red[tid] = d * d;
        } else {
            red[tid] = 0.0f;
        }
    }
    __syncthreads();

    if (tid == 0) {
        float s = 0.0f;
#pragma unroll
        for (int p = 0; p < TB; p++) s += red[p];
        g_part_bd[blockIdx.x] = s;
    }
}

// ---------------------------------------------------------------------------
// Final deterministic reduction -> out[0] = loss_bound, out[1] = loss_f
// ---------------------------------------------------------------------------
__global__ __launch_bounds__(THREADS)
void pinn_finalize(float* __restrict__ out, int nbi, int nbb,
                   int n_int, int n_bd)
{
    __shared__ float s[THREADS];
    const int tid = threadIdx.x;

    float a = 0.0f;
    for (int i = tid; i < nbi; i += THREADS) a += g_part_int[i];
    s[tid] = a;
    __syncthreads();
    for (int st = THREADS / 2; st > 0; st >>= 1) {
        if (tid < st) s[tid] += s[tid + st];
        __syncthreads();
    }
    float loss_f = 0.0f;
    if (tid == 0) loss_f = s[0] * (0.5f / (float)n_int);
    __syncthreads();

    float bsm = 0.0f;
    for (int i = tid; i < nbb; i += THREADS) bsm += g_part_bd[i];
    s[tid] = bsm;
    __syncthreads();
    for (int st = THREADS / 2; st > 0; st >>= 1) {
        if (tid < st) s[tid] += s[tid + st];
        __syncthreads();
    }
    if (tid == 0) {
        out[0] = s[0] * (0.5f / (float)n_bd); // loss_bound
        out[1] = loss_f;                      // loss_f
    }
}

// ---------------------------------------------------------------------------
extern "C" void kernel_launch(void* const* d_in, const int* in_sizes, int n_in,
                              void* d_out, int out_size)
{
    const float* xy_int = (const float*)d_in[0];
    const float* f      = (const float*)d_in[1];
    const float* xy_bd  = (const float*)d_in[2];
    const float* g      = (const float*)d_in[3];
    const float* W0     = (const float*)d_in[4];
    const float* b0     = (const float*)d_in[5];
    const float* W1     = (const float*)d_in[6];
    const float* b1     = (const float*)d_in[7];
    const float* W2     = (const float*)d_in[8];
    const float* b2     = (const float*)d_in[9];
    const float* W3     = (const float*)d_in[10];
    const float* b3     = (const float*)d_in[11];

    const int n_int = in_sizes[0] / 2;
    const int n_bd  = in_sizes[2] / 2;

    int gi = (n_int + TI - 1) / TI;
    int gb = (n_bd + TB - 1) / TB;
    if (gi > 65536) gi = 65536; // scratch bound (dataset: 8192)
    if (gb > 8192)  gb = 8192;  // scratch bound (dataset: 512)

    // dynamic smem: pair-packed activations + lap scratch
    const int smem_bytes = 4 * NP * H * (int)sizeof(ull)
                         + TI * (int)sizeof(float);   // 65664 B

    cudaFuncSetAttribute(pinn_interior,
                         cudaFuncAttributeMaxDynamicSharedMemorySize,
                         smem_bytes);

    pinn_interior<<<gi, THREADS, smem_bytes>>>(xy_int, f, W0, b0, W1, b1,
                                               W2, b2, W3, n_int);
    pinn_boundary<<<gb, THREADS>>>(xy_bd, g, W0, b0, W1, b1, W2, b2, W3, b3,
                                   n_bd);
    pinn_finalize<<<1, THREADS>>>((float*)d_out, gi, gb, n_int, n_bd);
}

// round 11
// speedup vs baseline: 1.7332x; 1.4321x over previous
#include <cuda_runtime.h>
#include <cuda_bf16.h>
#include <math.h>

#define H       128
#define PTS     32      // interior points per tile (M = 4*PTS = 128 rows)
#define TB      32      // boundary points per block
#define THREADS 256
#define NBLK    148

typedef unsigned int u32;

// Per-block partial sums (deterministic two-stage reduction; no device mallocs)
__device__ float g_part_int[65536];
__device__ float g_part_bd[8192];

// Accurate tanh independent of -use_fast_math lowering of tanhf.
__device__ __forceinline__ float my_tanh(float x)
{
    float ax = fabsf(x);
    float t  = __expf(-2.0f * ax);
    float r  = (1.0f - t) / (1.0f + t);
    return copysignf(r, x);
}

// ---------------- smem layout (bytes from dynamic base) ----------------
// bf16 tiles: 128 rows x 128 cols, 256 B/row, XOR-swizzled 16B chunks.
#define SM_AHI   0
#define SM_ALO   32768
#define SM_W1HI  65536
#define SM_W1LO  98304
#define SM_W2HI  131072
#define SM_W2LO  163840
#define SM_D     196608          // fp32 scratch: 128 rows x 68 floats
#define DSTRIDE  68
#define SM_XY    (SM_D + 128 * DSTRIDE * 4)   // 231424 (64 floats)
#define SM_SLAP  (SM_XY + 256)                 // 32 floats
#define SMEM_TOTAL (SM_SLAP + 128)             // 231808 B

// swizzled byte offset inside a bf16 tile: 16B chunk index ^= (row & 7)
__device__ __forceinline__ u32 toff(int row, int col)
{
    return (u32)(row * 256 + ((((col >> 3) ^ (row & 7)) << 4)) + (col & 7) * 2);
}

__device__ __forceinline__ u32 smem_to_u32(const void* p)
{
    u32 a;
    asm("{ .reg .u64 t; cvta.to.shared.u64 t, %1; cvt.u32.u64 %0, t; }"
        : "=r"(a) : "l"(p));
    return a;
}

__device__ __forceinline__ void ldsm4(u32* r, u32 addr)
{
    asm volatile("ldmatrix.sync.aligned.m8n8.x4.shared.b16 {%0,%1,%2,%3}, [%4];"
                 : "=r"(r[0]), "=r"(r[1]), "=r"(r[2]), "=r"(r[3]) : "r"(addr));
}

__device__ __forceinline__ void mma_bf16(float* c, const u32* a, u32 b0, u32 b1)
{
    asm volatile(
        "mma.sync.aligned.m16n8k16.row.col.f32.bf16.bf16.f32 "
        "{%0,%1,%2,%3}, {%4,%5,%6,%7}, {%8,%9}, {%0,%1,%2,%3};"
        : "+f"(c[0]), "+f"(c[1]), "+f"(c[2]), "+f"(c[3])
        : "r"(a[0]), "r"(a[1]), "r"(a[2]), "r"(a[3]), "r"(b0), "r"(b1));
}

__device__ __forceinline__ u32 pack2bf(float a, float b)
{
    return ((u32)__bfloat16_as_ushort(__float2bfloat16(b)) << 16)
         |  (u32)__bfloat16_as_ushort(__float2bfloat16(a));
}

// ---------------------------------------------------------------------------
// 3-term bf16-split GEMM mainloop: D[128,128] += Ahi*Bhi + Ahi*Blo + Alo*Bhi.
// Warp w computes rows 16w..16w+15, all 128 cols; acc[16][4] per thread.
// ---------------------------------------------------------------------------
__device__ __forceinline__ void mainloop(u32 smb, u32 ahi, u32 alo,
                                         u32 whi, u32 wlo,
                                         int lane, int w, float acc[16][4])
{
#pragma unroll
    for (int i = 0; i < 16; i++)
#pragma unroll
        for (int j = 0; j < 4; j++) acc[i][j] = 0.0f;

    const int arow = w * 16 + (lane & 15);
    const int ahi4 = lane >> 4;               // 0/1 -> k +8
    const int brl  = ((lane >> 4) & 1) * 8 + (lane & 7);
    const int bko  = (lane >> 3) & 1;         // 0/1 -> k chunk +1

#pragma unroll 2
    for (int s = 0; s < 8; s++) {
        u32 aoffs = (u32)(arow * 256 + (((s * 2 + ahi4) ^ (arow & 7)) << 4));
        u32 ah[4], al[4];
        ldsm4(ah, smb + ahi + aoffs);
        ldsm4(al, smb + alo + aoffs);

        u32 bh[32], bl[32], boffs[8];
#pragma unroll
        for (int jp = 0; jp < 8; jp++) {
            int brow = jp * 16 + brl;
            boffs[jp] = (u32)(brow * 256 + (((s * 2 + bko) ^ (brow & 7)) << 4));
            ldsm4(&bh[jp * 4], smb + whi + boffs[jp]);
        }
#pragma unroll
        for (int jp = 0; jp < 8; jp++)
            ldsm4(&bl[jp * 4], smb + wlo + boffs[jp]);

#pragma unroll
        for (int jp = 0; jp < 8; jp++) {      // hi * hi
            mma_bf16(acc[2 * jp],     ah, bh[4 * jp],     bh[4 * jp + 1]);
            mma_bf16(acc[2 * jp + 1], ah, bh[4 * jp + 2], bh[4 * jp + 3]);
        }
#pragma unroll
        for (int jp = 0; jp < 8; jp++) {      // hi * lo
            mma_bf16(acc[2 * jp],     ah, bl[4 * jp],     bl[4 * jp + 1]);
            mma_bf16(acc[2 * jp + 1], ah, bl[4 * jp + 2], bl[4 * jp + 3]);
        }
#pragma unroll
        for (int jp = 0; jp < 8; jp++) {      // lo * hi
            mma_bf16(acc[2 * jp],     al, bh[4 * jp],     bh[4 * jp + 1]);
            mma_bf16(acc[2 * jp + 1], al, bh[4 * jp + 2], bh[4 * jp + 3]);
        }
    }
}

// Store one 64-col half of D (n-tiles ch*8..ch*8+7) to fp32 smem scratch.
__device__ __forceinline__ void store_D_half(char* sm, const float acc[16][4],
                                             int w, int lane, int ch)
{
    const int g = lane >> 2, q = lane & 3;
    float* D = (float*)(sm + SM_D);
#pragma unroll
    for (int nt8 = 0; nt8 < 8; nt8++) {
        const int nt  = ch * 8 + nt8;
        const int col = nt8 * 8 + q * 2;
        *(float2*)&D[(w * 16 + g) * DSTRIDE + col] =
            make_float2(acc[nt][0], acc[nt][1]);
        *(float2*)&D[(w * 16 + g + 8) * DSTRIDE + col] =
            make_float2(acc[nt][2], acc[nt][3]);
    }
}

// Hidden epilogue for one 64-col half: tanh chain on D, write new A hi/lo.
__device__ __forceinline__ void epi_hidden_half(char* sm,
                                                const float* __restrict__ b,
                                                int tid, int ch)
{
    const int p = tid >> 3, q8 = tid & 7;
    const float* D = (const float*)(sm + SM_D);

    float d[4][8];
#pragma unroll
    for (int c = 0; c < 4; c++) {
        const float* r = &D[(4 * p + c) * DSTRIDE + q8 * 8];
        *(float4*)&d[c][0] = *(const float4*)&r[0];
        *(float4*)&d[c][4] = *(const float4*)&r[4];
    }

    const int colg = ch * 64 + q8 * 8;
    float o[4][8];
#pragma unroll
    for (int i = 0; i < 8; i++) {
        float a  = my_tanh(d[0][i] + __ldg(&b[colg + i]));
        float t1 = 1.0f - a * a;
        float t2 = -2.0f * a * t1;
        o[0][i] = a;
        o[1][i] = t1 * d[1][i];
        o[2][i] = t1 * d[2][i];
        o[3][i] = fmaf(t2, fmaf(d[1][i], d[1][i], d[2][i] * d[2][i]),
                       t1 * d[3][i]);
    }

    const int chunk = ch * 8 + q8;
#pragma unroll
    for (int c = 0; c < 4; c++) {
        const int row = 4 * p + c;
        const u32 off = (u32)(row * 256 + ((chunk ^ (row & 7)) << 4));
        u32 hi[4], lo[4];
#pragma unroll
        for (int ii = 0; ii < 4; ii++) {
            float v0 = o[c][2 * ii], v1 = o[c][2 * ii + 1];
            float h0 = __bfloat162float(__float2bfloat16(v0));
            float h1 = __bfloat162float(__float2bfloat16(v1));
            hi[ii] = pack2bf(v0, v1);
            lo[ii] = pack2bf(v0 - h0, v1 - h1);
        }
        *(uint4*)(sm + SM_AHI + off) = make_uint4(hi[0], hi[1], hi[2], hi[3]);
        *(uint4*)(sm + SM_ALO + off) = make_uint4(lo[0], lo[1], lo[2], lo[3]);
    }
}

// Output epilogue for one half: partial lap = sum_cols L * W3.
__device__ __forceinline__ float epi_out_half(char* sm,
                                              const float* __restrict__ b2,
                                              const float* __restrict__ W3,
                                              int tid, int ch)
{
    const int p = tid >> 3, q8 = tid & 7;
    const float* D = (const float*)(sm + SM_D);

    float d[4][8];
#pragma unroll
    for (int c = 0; c < 4; c++) {
        const float* r = &D[(4 * p + c) * DSTRIDE + q8 * 8];
        *(float4*)&d[c][0] = *(const float4*)&r[0];
        *(float4*)&d[c][4] = *(const float4*)&r[4];
    }

    const int colg = ch * 64 + q8 * 8;
    float s = 0.0f;
#pragma unroll
    for (int i = 0; i < 8; i++) {
        float a  = my_tanh(d[0][i] + __ldg(&b2[colg + i]));
        float t1 = 1.0f - a * a;
        float t2 = -2.0f * a * t1;
        float L  = fmaf(t2, fmaf(d[1][i], d[1][i], d[2][i] * d[2][i]),
                        t1 * d[3][i]);
        s = fmaf(L, __ldg(&W3[colg + i]), s);
    }
    return s;
}

// ---------------------------------------------------------------------------
// Interior: HMMA bf16-split Taylor-mode Laplacian. Persistent CTAs.
// GEMM rows: r = p*4 + c (p = point 0..31; c = v, gx, gy, L).
// ---------------------------------------------------------------------------
__global__ __launch_bounds__(THREADS, 1)
void pinn_interior(const float* __restrict__ xy, const float* __restrict__ f,
                   const float* __restrict__ W0, const float* __restrict__ b0,
                   const float* __restrict__ W1, const float* __restrict__ b1,
                   const float* __restrict__ W2, const float* __restrict__ b2,
                   const float* __restrict__ W3, int n, int ntiles)
{
    extern __shared__ __align__(128) char sm[];
    const u32 smb = smem_to_u32(sm);

    const int tid  = threadIdx.x;
    const int w    = tid >> 5;
    const int lane = tid & 31;

    float* XY   = (float*)(sm + SM_XY);
    float* SLAP = (float*)(sm + SM_SLAP);

    // ---- one-time: split + transpose W1/W2 into bf16 hi/lo B^T tiles ----
    for (int idx = tid; idx < H * H; idx += THREADS) {
        int k = idx >> 7, nn = idx & 127;     // W[k][nn], coalesced over nn
        u32 off = toff(nn, k);                // B^T cell (row=n, col=k)
        float w1 = W1[idx], w2 = W2[idx];
        __nv_bfloat16 h1 = __float2bfloat16(w1);
        __nv_bfloat16 h2 = __float2bfloat16(w2);
        *(__nv_bfloat16*)(sm + SM_W1HI + off) = h1;
        *(__nv_bfloat16*)(sm + SM_W1LO + off) = __float2bfloat16(w1 - __bfloat162float(h1));
        *(__nv_bfloat16*)(sm + SM_W2HI + off) = h2;
        *(__nv_bfloat16*)(sm + SM_W2LO + off) = __float2bfloat16(w2 - __bfloat162float(h2));
    }
    __syncthreads();

    for (int tile = blockIdx.x; tile < ntiles; tile += gridDim.x) {
        const int base = tile * PTS;

        if (tid < PTS * 2) {
            int pt = base + (tid >> 1); if (pt > n - 1) pt = n - 1;
            XY[tid] = xy[pt * 2 + (tid & 1)];
        }
        __syncthreads();

        // ---- layer 0 seed -> A hi/lo tiles ----
        for (int it = tid; it < PTS * 64; it += THREADS) {
            int p = it >> 6, j0 = (it & 63) * 2;
            float x = XY[p * 2], y = XY[p * 2 + 1];
            float o[2][4];
#pragma unroll
            for (int jj = 0; jj < 2; jj++) {
                int j = j0 + jj;
                float wx = __ldg(&W0[j]), wy = __ldg(&W0[H + j]);
                float zv = fmaf(x, wx, fmaf(y, wy, __ldg(&b0[j])));
                float a  = my_tanh(zv);
                float t1 = 1.0f - a * a;
                float t2 = -2.0f * a * t1;
                o[jj][0] = a;
                o[jj][1] = t1 * wx;
                o[jj][2] = t1 * wy;
                o[jj][3] = t2 * fmaf(wx, wx, wy * wy);
            }
#pragma unroll
            for (int c = 0; c < 4; c++) {
                u32 off = toff(p * 4 + c, j0);
                float v0 = o[0][c], v1 = o[1][c];
                float h0 = __bfloat162float(__float2bfloat16(v0));
                float h1 = __bfloat162float(__float2bfloat16(v1));
                *(u32*)(sm + SM_AHI + off) = pack2bf(v0, v1);
                *(u32*)(sm + SM_ALO + off) = pack2bf(v0 - h0, v1 - h1);
            }
        }
        __syncthreads();

        float acc[16][4];

        // ---- layer 1 ----
        mainloop(smb, SM_AHI, SM_ALO, SM_W1HI, SM_W1LO, lane, w, acc);
        store_D_half(sm, acc, w, lane, 0);
        __syncthreads();
        epi_hidden_half(sm, b1, tid, 0);
        __syncthreads();
        store_D_half(sm, acc, w, lane, 1);
        __syncthreads();
        epi_hidden_half(sm, b1, tid, 1);
        __syncthreads();

        // ---- layer 2 + output projection ----
        mainloop(smb, SM_AHI, SM_ALO, SM_W2HI, SM_W2LO, lane, w, acc);
        store_D_half(sm, acc, w, lane, 0);
        __syncthreads();
        float s = epi_out_half(sm, b2, W3, tid, 0);
        __syncthreads();
        store_D_half(sm, acc, w, lane, 1);
        __syncthreads();
        s += epi_out_half(sm, b2, W3, tid, 1);

        s += __shfl_xor_sync(0xffffffffu, s, 1);
        s += __shfl_xor_sync(0xffffffffu, s, 2);
        s += __shfl_xor_sync(0xffffffffu, s, 4);
        if ((tid & 7) == 0) SLAP[tid >> 3] = s;
        __syncthreads();

        if (tid == 0) {
            float ssum = 0.0f;
#pragma unroll
            for (int p = 0; p < PTS; p++) {
                int idx = base + p;
                if (idx < n) {
                    float d = SLAP[p] - f[idx];
                    ssum = fmaf(d, d, ssum);
                }
            }
            g_part_int[tile] = ssum;
        }
        __syncthreads();
    }
}

// ---------------------------------------------------------------------------
// Boundary: plain fp32 forward + squared residual (small workload, unchanged).
// ---------------------------------------------------------------------------
__device__ __forceinline__ void hidden1(const float* __restrict__ in,
                                        float* __restrict__ outp,
                                        const float* __restrict__ W,
                                        const float* __restrict__ b,
                                        int j, int p0)
{
    float acc[TB / 2];
#pragma unroll
    for (int p = 0; p < TB / 2; p++) acc[p] = 0.0f;

#pragma unroll 1
    for (int k = 0; k < H; k += 4) {
        const float w0 = W[(k + 0) * H + j];
        const float w1 = W[(k + 1) * H + j];
        const float w2 = W[(k + 2) * H + j];
        const float w3 = W[(k + 3) * H + j];
#pragma unroll
        for (int p = 0; p < TB / 2; p++) {
            const float4 a = *reinterpret_cast<const float4*>(&in[(p0 + p) * H + k]);
            acc[p] = fmaf(a.x, w0, fmaf(a.y, w1, fmaf(a.z, w2, fmaf(a.w, w3, acc[p]))));
        }
    }
    const float bj = b[j];
#pragma unroll
    for (int p = 0; p < TB / 2; p++)
        outp[(p0 + p) * H + j] = my_tanh(acc[p] + bj);
}

__global__ __launch_bounds__(THREADS)
void pinn_boundary(const float* __restrict__ xy, const float* __restrict__ g,
                   const float* __restrict__ W0, const float* __restrict__ b0,
                   const float* __restrict__ W1, const float* __restrict__ b1,
                   const float* __restrict__ W2, const float* __restrict__ b2,
                   const float* __restrict__ W3, const float* __restrict__ b3,
                   int n)
{
    __shared__ __align__(16) float A[TB * H];
    __shared__ __align__(16) float B[TB * H];
    __shared__ float sxy[TB * 2];
    __shared__ float red[TB];

    const int tid  = threadIdx.x;
    const int j    = tid & (H - 1);
    const int p0   = (tid >> 7) * (TB / 2);
    const int base = blockIdx.x * TB;

    if (tid < TB * 2) {
        int pt = base + (tid >> 1);
        if (pt > n - 1) pt = n - 1;
        sxy[tid] = xy[pt * 2 + (tid & 1)];
    }
    __syncthreads();

    {
        const float w0x = W0[j], w0y = W0[H + j], bj = b0[j];
#pragma unroll
        for (int p = 0; p < TB / 2; p++) {
            const int pp = p0 + p;
            A[pp * H + j] = my_tanh(fmaf(sxy[pp * 2], w0x, fmaf(sxy[pp * 2 + 1], w0y, bj)));
        }
    }
    __syncthreads();
    hidden1(A, B, W1, b1, j, p0);
    __syncthreads();
    hidden1(B, A, W2, b2, j, p0);
    __syncthreads();

    if (tid < TB) {
        float v = b3[0];
        for (int k = 0; k < H; k++) v = fmaf(A[tid * H + k], W3[k], v);
        int idx = base + tid;
        if (idx < n) { float d = v - g[idx]; red[tid] = d * d; }
        else red[tid] = 0.0f;
    }
    __syncthreads();

    if (tid == 0) {
        float s = 0.0f;
#pragma unroll
        for (int p = 0; p < TB; p++) s += red[p];
        g_part_bd[blockIdx.x] = s;
    }
}

// ---------------------------------------------------------------------------
__global__ __launch_bounds__(THREADS)
void pinn_finalize(float* __restrict__ out, int nbi, int nbb, int n_int, int n_bd)
{
    __shared__ float s[THREADS];
    const int tid = threadIdx.x;

    float a = 0.0f;
    for (int i = tid; i < nbi; i += THREADS) a += g_part_int[i];
    s[tid] = a;
    __syncthreads();
    for (int st = THREADS / 2; st > 0; st >>= 1) {
        if (tid < st) s[tid] += s[tid + st];
        __syncthreads();
    }
    float loss_f = 0.0f;
    if (tid == 0) loss_f = s[0] * (0.5f / (float)n_int);
    __syncthreads();

    float bsm = 0.0f;
    for (int i = tid; i < nbb; i += THREADS) bsm += g_part_bd[i];
    s[tid] = bsm;
    __syncthreads();
    for (int st = THREADS / 2; st > 0; st >>= 1) {
        if (tid < st) s[tid] += s[tid + st];
        __syncthreads();
    }
    if (tid == 0) {
        out[0] = s[0] * (0.5f / (float)n_bd);
        out[1] = loss_f;
    }
}

// ---------------------------------------------------------------------------
extern "C" void kernel_launch(void* const* d_in, const int* in_sizes, int n_in,
                              void* d_out, int out_size)
{
    const float* xy_int = (const float*)d_in[0];
    const float* f      = (const float*)d_in[1];
    const float* xy_bd  = (const float*)d_in[2];
    const float* g      = (const float*)d_in[3];
    const float* W0     = (const float*)d_in[4];
    const float* b0     = (const float*)d_in[5];
    const float* W1     = (const float*)d_in[6];
    const float* b1     = (const float*)d_in[7];
    const float* W2     = (const float*)d_in[8];
    const float* b2     = (const float*)d_in[9];
    const float* W3     = (const float*)d_in[10];
    const float* b3     = (const float*)d_in[11];

    const int n_int = in_sizes[0] / 2;
    const int n_bd  = in_sizes[2] / 2;

    int ntiles = (n_int + PTS - 1) / PTS;
    if (ntiles > 65536) ntiles = 65536;   // scratch bound (dataset: 8192)
    int gb = (n_bd + TB - 1) / TB;
    if (gb > 8192) gb = 8192;             // scratch bound (dataset: 512)

    int gi = NBLK < ntiles ? NBLK : ntiles;

    cudaFuncSetAttribute(pinn_interior,
                         cudaFuncAttributeMaxDynamicSharedMemorySize, SMEM_TOTAL);

    pinn_interior<<<gi, THREADS, SMEM_TOTAL>>>(xy_int, f, W0, b0, W1, b1,
                                               W2, b2, W3, n_int, ntiles);
    pinn_boundary<<<gb, THREADS>>>(xy_bd, g, W0, b0, W1, b1, W2, b2, W3, b3, n_bd);
    pinn_finalize<<<1, THREADS>>>((float*)d_out, ntiles, gb, n_int, n_bd);
}